// round 4
// baseline (speedup 1.0000x reference)
#include <cuda_runtime.h>
#include <math.h>

#define D_DIM     512
#define N_WAY     64
#define CTA_ROWS  256
#define SMEM_STRIDE 68   // floats per k-row: 68*4 = 272 B -> 16B aligned rows, spreads banks
#define SMEM_FLOATS (D_DIM * SMEM_STRIDE + N_WAY)
#define SMEM_BYTES  (SMEM_FLOATS * sizeof(float))

// Scratch for prototype norms (allocation-free per harness rules)
__device__ float g_pn[N_WAY];

// ---------------------------------------------------------------------------
// Prep: per-prototype L2 norm. 64 blocks x 128 threads, trivial cost.
// ---------------------------------------------------------------------------
__global__ void proto_norm_kernel(const float* __restrict__ protos) {
    __shared__ float red[128];
    int c = blockIdx.x;
    int t = threadIdx.x;
    const float* p = protos + c * D_DIM;
    float s = 0.f;
    for (int k = t; k < D_DIM; k += 128) {
        float v = p[k];
        s = fmaf(v, v, s);
    }
    red[t] = s;
    __syncthreads();
    for (int off = 64; off > 0; off >>= 1) {
        if (t < off) red[t] += red[t + off];
        __syncthreads();
    }
    if (t == 0) g_pn[c] = sqrtf(red[0]);
}

// ---------------------------------------------------------------------------
// Main: one x-row per thread, all 64 prototypes, packed f32x2 FMA.
// smem: protos transposed [k][c] (stride 68) + pn[64].
// ---------------------------------------------------------------------------
__device__ __forceinline__ unsigned long long pack_dup(float v) {
    unsigned long long r;
    asm("mov.b64 %0, {%1, %1};" : "=l"(r) : "f"(v));
    return r;
}

__global__ __launch_bounds__(CTA_ROWS, 1)
void cosine_kernel(const float* __restrict__ x,
                   const float* __restrict__ protos,
                   float* __restrict__ out,
                   int Brows) {
    extern __shared__ float smem[];
    float* sproT = smem;                       // [512][68] transposed protos
    float* spn   = smem + D_DIM * SMEM_STRIDE; // [64] proto norms

    const int tid = threadIdx.x;

    // Cooperative transposed fill of prototypes (coalesced gmem reads).
    #pragma unroll 4
    for (int i = tid; i < N_WAY * D_DIM; i += CTA_ROWS) {
        int c = i >> 9;        // i / 512
        int k = i & (D_DIM - 1);
        sproT[k * SMEM_STRIDE + c] = protos[i];
    }
    if (tid < N_WAY) spn[tid] = g_pn[tid];
    __syncthreads();

    const int row = blockIdx.x * CTA_ROWS + tid;
    if (row >= Brows) return;

    // 32 packed accumulators: acc[a] covers prototype columns (2a, 2a+1)
    unsigned long long acc[32];
    #pragma unroll
    for (int i = 0; i < 32; ++i) acc[i] = 0ull;

    float xx = 0.f;  // ||x_row||^2
    const float4* xr = reinterpret_cast<const float4*>(x + (size_t)row * D_DIM);

    #pragma unroll 1
    for (int k4 = 0; k4 < D_DIM / 4; ++k4) {
        float4 xv = xr[k4];
        xx = fmaf(xv.x, xv.x, xx);
        xx = fmaf(xv.y, xv.y, xx);
        xx = fmaf(xv.z, xv.z, xx);
        xx = fmaf(xv.w, xv.w, xx);
        float xs[4] = {xv.x, xv.y, xv.z, xv.w};
        #pragma unroll
        for (int j = 0; j < 4; ++j) {
            unsigned long long xp = pack_dup(xs[j]);
            const float* prow = &sproT[(k4 * 4 + j) * SMEM_STRIDE];
            #pragma unroll
            for (int c4 = 0; c4 < 16; ++c4) {
                // Whole-warp broadcast LDS.128: two f32x2 prototype pairs
                ulonglong2 pp = *reinterpret_cast<const ulonglong2*>(prow + c4 * 4);
                asm("fma.rn.f32x2 %0, %1, %2, %0;"
                    : "+l"(acc[2 * c4])     : "l"(xp), "l"(pp.x));
                asm("fma.rn.f32x2 %0, %1, %2, %0;"
                    : "+l"(acc[2 * c4 + 1]) : "l"(xp), "l"(pp.y));
            }
        }
    }

    const float xn = sqrtf(xx);
    float* orow = out + (size_t)row * N_WAY;
    #pragma unroll
    for (int c4 = 0; c4 < 16; ++c4) {
        float o0, o1, o2, o3;
        asm("mov.b64 {%0, %1}, %2;" : "=f"(o0), "=f"(o1) : "l"(acc[2 * c4]));
        asm("mov.b64 {%0, %1}, %2;" : "=f"(o2), "=f"(o3) : "l"(acc[2 * c4 + 1]));
        float4 r;
        r.x = -o0 / fmaxf(xn * spn[c4 * 4 + 0], 1e-8f);
        r.y = -o1 / fmaxf(xn * spn[c4 * 4 + 1], 1e-8f);
        r.z = -o2 / fmaxf(xn * spn[c4 * 4 + 2], 1e-8f);
        r.w = -o3 / fmaxf(xn * spn[c4 * 4 + 3], 1e-8f);
        reinterpret_cast<float4*>(orow)[c4] = r;
    }
}

// ---------------------------------------------------------------------------
// Launch: inputs per metadata order: x [B*512], prototypes [64*512]; out fp32.
// Graph-capturable: two plain kernel launches, no sync/alloc.
// ---------------------------------------------------------------------------
extern "C" void kernel_launch(void* const* d_in, const int* in_sizes, int n_in,
                              void* d_out, int out_size) {
    const float* x      = (const float*)d_in[0];
    const float* protos = (const float*)d_in[1];
    float* out          = (float*)d_out;
    const int Brows = in_sizes[0] / D_DIM;

    // Idempotent, host-side config (not a stream op; capture-safe).
    cudaFuncSetAttribute(cosine_kernel,
                         cudaFuncAttributeMaxDynamicSharedMemorySize,
                         (int)SMEM_BYTES);

    proto_norm_kernel<<<N_WAY, 128>>>(protos);
    cosine_kernel<<<(Brows + CTA_ROWS - 1) / CTA_ROWS, CTA_ROWS, SMEM_BYTES>>>(
        x, protos, out, Brows);
}